// round 1
// baseline (speedup 1.0000x reference)
#include <cuda_runtime.h>

#define OUT_H   32
#define OUT_W   256
#define IMG_H   256
#define IMG_W   512
#define D_SIZE  287      // d = i - ii + 255  in [0, 286]
#define E_SIZE  767      // e = j - ij + 511  in [0, 766]
#define E_PAD   768
#define NCHUNK  256      // one block per image row ii

__device__ float g_K[D_SIZE * E_PAD];
__device__ float g_part[NCHUNK * OUT_H * OUT_W];   // 8 MB partials

// ---------------------------------------------------------------------------
// Kernel 1: build the Toeplitz weight table (220K reciprocals instead of 1.07e9)
// ---------------------------------------------------------------------------
__global__ void fill_k_kernel(const float* __restrict__ pos) {
    int d = blockIdx.x;
    float dx  = (float)(d - 255) + pos[0];
    float dx2 = dx * dx;
    for (int e = threadIdx.x; e < E_PAD; e += blockDim.x) {
        float dy = (float)(e - 511) + pos[1];
        g_K[d * E_PAD + e] = 1.0f / (dx2 + dy * dy);
    }
}

// ---------------------------------------------------------------------------
// Kernel 2: for image row ii, accumulate its contribution to ALL 32x256 outputs.
//   partial[ii][i][j] = sum_ij img[ii][ij] * K[i-ii+255][j-ij+511]
// Thread tile: 4 i-rows x 8 consecutive j. 256 threads = 8 ig x 32 jg covers
// the whole 32x256 output. Per-thread sliding 16-float window per K row:
// per 8 inner steps -> 256 FMAs vs 2 LDG.128 per row + 8 broadcast LDS.
// ---------------------------------------------------------------------------
__global__ void __launch_bounds__(256, 2) conv_part_kernel(const float* __restrict__ img) {
    __shared__ float simg[IMG_W];
    const int ii  = blockIdx.x;
    const int tid = threadIdx.x;

    // cooperative load of image row ii (512 floats)
    {
        const float2* src = (const float2*)(img + ii * IMG_W);
        ((float2*)simg)[tid] = src[tid];
    }
    __syncthreads();

    const int jg = tid & 31;        // 32 j-groups, j = 8*jg + jj
    const int ig = tid >> 5;        // 8 i-groups,  i = 4*ig + r
    const int i0 = ig * 4;
    const float* Kb = g_K + (i0 - ii + 255) * E_PAD;   // row for r=0; +E_PAD per r
    const int x0 = 8 * jg + 511;    // e-index for (jj=0, ij=0)

    float acc[4][8];
#pragma unroll
    for (int r = 0; r < 4; r++)
#pragma unroll
        for (int jj = 0; jj < 8; jj++) acc[r][jj] = 0.0f;

    // window w[r][k] = K[row_r][x0 - 8g - 7 + k]   (k in [0,15]; k=15 unused)
    float w[4][16];
#pragma unroll
    for (int r = 0; r < 4; r++) {
        const float4* p = (const float4*)(Kb + r * E_PAD + (x0 - 7));  // 16B aligned
        float4 v0 = p[0], v1 = p[1], v2 = p[2], v3 = p[3];
        w[r][0]  = v0.x; w[r][1]  = v0.y; w[r][2]  = v0.z; w[r][3]  = v0.w;
        w[r][4]  = v1.x; w[r][5]  = v1.y; w[r][6]  = v1.z; w[r][7]  = v1.w;
        w[r][8]  = v2.x; w[r][9]  = v2.y; w[r][10] = v2.z; w[r][11] = v2.w;
        w[r][12] = v3.x; w[r][13] = v3.y; w[r][14] = v3.z; w[r][15] = v3.w;
    }

    // body for one group of 8 ij-steps: acc[r][jj] += s(ij) * K[row_r][x0 - ij + jj]
#define GROUP_BODY(g_)                                                        \
    {                                                                         \
        _Pragma("unroll")                                                     \
        for (int t = 0; t < 8; t++) {                                         \
            float s = simg[(g_) * 8 + t];                                     \
            _Pragma("unroll")                                                 \
            for (int r = 0; r < 4; r++) {                                     \
                _Pragma("unroll")                                             \
                for (int jj = 0; jj < 8; jj++)                                \
                    acc[r][jj] += s * w[r][7 - t + jj];                       \
            }                                                                 \
        }                                                                     \
    }

    for (int g = 0; g < 63; g++) {
        GROUP_BODY(g);
        // slide window down by 8: w[k+8] = w[k], refill lower 8 with 2x LDG.128
#pragma unroll
        for (int r = 0; r < 4; r++) {
#pragma unroll
            for (int k = 7; k >= 0; k--) w[r][k + 8] = w[r][k];
            const float4* p = (const float4*)(Kb + r * E_PAD + (x0 - 8 * (g + 1) - 7));
            float4 v0 = p[0], v1 = p[1];
            w[r][0] = v0.x; w[r][1] = v0.y; w[r][2] = v0.z; w[r][3] = v0.w;
            w[r][4] = v1.x; w[r][5] = v1.y; w[r][6] = v1.z; w[r][7] = v1.w;
        }
    }
    GROUP_BODY(63);
#undef GROUP_BODY

    // write partials (coalesced 16B stores)
    float* dst = g_part + ii * (OUT_H * OUT_W);
#pragma unroll
    for (int r = 0; r < 4; r++) {
        float4* q = (float4*)(dst + (i0 + r) * OUT_W + 8 * jg);
        q[0] = make_float4(acc[r][0], acc[r][1], acc[r][2], acc[r][3]);
        q[1] = make_float4(acc[r][4], acc[r][5], acc[r][6], acc[r][7]);
    }
}

// ---------------------------------------------------------------------------
// Kernel 3: sum the 256 partials per output element (deterministic, no atomics)
// ---------------------------------------------------------------------------
__global__ void reduce_kernel(float* __restrict__ out) {
    int o = blockIdx.x * blockDim.x + threadIdx.x;   // 0..8191
    float s0 = 0.f, s1 = 0.f, s2 = 0.f, s3 = 0.f;
#pragma unroll 4
    for (int c = 0; c < NCHUNK; c += 4) {
        s0 += g_part[(c + 0) * (OUT_H * OUT_W) + o];
        s1 += g_part[(c + 1) * (OUT_H * OUT_W) + o];
        s2 += g_part[(c + 2) * (OUT_H * OUT_W) + o];
        s3 += g_part[(c + 3) * (OUT_H * OUT_W) + o];
    }
    out[o] = (s0 + s1) + (s2 + s3);
}

// ---------------------------------------------------------------------------
extern "C" void kernel_launch(void* const* d_in, const int* in_sizes, int n_in,
                              void* d_out, int out_size) {
    const float* img = (const float*)d_in[0];   // [256, 512] f32
    const float* pos = (const float*)d_in[1];   // [2] f32
    float* out = (float*)d_out;                 // [32, 256] f32

    fill_k_kernel<<<D_SIZE, 256>>>(pos);
    conv_part_kernel<<<NCHUNK, 256>>>(img);
    reduce_kernel<<<(OUT_H * OUT_W) / 256, 256>>>(out);
}